// round 1
// baseline (speedup 1.0000x reference)
#include <cuda_runtime.h>
#include <cstdint>

// ---------------- problem constants ----------------
#define MLIB   200000
#define NPATCH 676
#define NPAD   768
#define DDIM   384
#define IMG    224
#define HWDIM  26
#define KTOP   5
#define SIGMA  4.0f
#define KRAD   16          // (KS-1)/2, KS=33

// ---------------- device scratch (no allocations allowed) ----------------
__device__ __align__(16) float g_patchN[NPAD * DDIM];   // normalized patch, zero-padded rows
__device__ float g_pn[NPAD];                            // ||patchN_row||^2 (== pn in reference)
__device__ float g_ln[MLIB];                            // ||lib_row||^2
__device__ unsigned long long g_minpack[NPATCH];        // (d2_bits<<32)|lib_idx  per patch
__device__ float g_dstar[MLIB];                         // d2 from m_star to lib
__device__ int   g_nn[KTOP];
struct Scal { int s_idx; float s_star; int m_idx; float msn; };
__device__ Scal  g_scal;
__device__ float g_mt[DDIM];                            // m_test_star
__device__ float g_ms[DDIM];                            // m_star
__device__ float g_map1[IMG * IMG];
__device__ float g_map2[IMG * IMG];

// ---------------- K1: init + L2-normalize patch rows, compute pn ----------------
__global__ void k_norm(const float* __restrict__ patch) {
    int row = blockIdx.x;          // 0..767
    int t = threadIdx.x;           // 128 threads
    __shared__ float red[128];

    if (t == 0 && row < NPATCH) g_minpack[row] = ~0ull;

    float s = 0.f;
    if (row < NPATCH) {
        for (int c = t; c < DDIM; c += 128) { float v = patch[row * DDIM + c]; s += v * v; }
    }
    red[t] = s; __syncthreads();
    for (int st = 64; st > 0; st >>= 1) { if (t < st) red[t] += red[t + st]; __syncthreads(); }
    float inv = 0.f;
    if (row < NPATCH) { float n = sqrtf(red[0]); inv = 1.f / fmaxf(n, 1e-12f); }
    __syncthreads();

    float s2 = 0.f;
    for (int c = t; c < DDIM; c += 128) {
        float y = (row < NPATCH) ? patch[row * DDIM + c] * inv : 0.f;
        g_patchN[row * DDIM + c] = y;
        s2 += y * y;
    }
    red[t] = s2; __syncthreads();
    for (int st = 64; st > 0; st >>= 1) { if (t < st) red[t] += red[t + st]; __syncthreads(); }
    if (t == 0) g_pn[row] = (row < NPATCH) ? red[0] : 0.f;
}

// ---------------- K2: ln[j] = ||lib_j||^2 (warp per row) ----------------
__global__ void k_ln(const float* __restrict__ lib) {
    int row  = blockIdx.x * 8 + (threadIdx.x >> 5);   // grid 25000 x 256 -> 200000 rows
    int lane = threadIdx.x & 31;
    const float* p = lib + (size_t)row * DDIM;
    float s = 0.f;
    for (int c = lane; c < DDIM; c += 32) { float v = p[c]; s += v * v; }
    #pragma unroll
    for (int o = 16; o > 0; o >>= 1) s += __shfl_down_sync(0xffffffffu, s, o);
    if (lane == 0) g_ln[row] = s;
}

// ---------------- K3: fused distance GEMM + per-patch min/argmin ----------------
#define TM 128
#define TN 128
#define TK 16
#define NKT (DDIM / TK)   // 24

__global__ __launch_bounds__(256, 2) void k_gemm(const float* __restrict__ lib) {
    __shared__ __align__(16) float As[2][TK][TM];
    __shared__ __align__(16) float Bs[2][TK][TN];
    __shared__ unsigned long long colmin[TN];

    const int bm = blockIdx.y * TM;    // lib chunk
    const int bn = blockIdx.x * TN;    // patch chunk (padded to 768)
    const int tid = threadIdx.x;
    if (tid < TN) colmin[tid] = ~0ull;

    const int m0 = (tid >> 4) << 3;
    const int n0 = (tid & 15) << 3;

    float acc[8][8];
    #pragma unroll
    for (int i = 0; i < 8; i++)
        #pragma unroll
        for (int j = 0; j < 8; j++) acc[i][j] = 0.f;

    float4 pa[2], pb[2];

    auto gload = [&](int kt) {
        int k0 = kt * TK;
        #pragma unroll
        for (int v = 0; v < 2; v++) {
            int lin = tid + v * 256;              // 512 float4 slots per operand
            int r = lin >> 2, c4 = (lin & 3) << 2;
            int gm = bm + r;
            float4 a = make_float4(0.f, 0.f, 0.f, 0.f);
            if (gm < MLIB) a = *(const float4*)(lib + (size_t)gm * DDIM + k0 + c4);
            pa[v] = a;
            pb[v] = *(const float4*)(g_patchN + (size_t)(bn + r) * DDIM + k0 + c4);
        }
    };
    auto sstore = [&](int buf) {
        #pragma unroll
        for (int v = 0; v < 2; v++) {
            int lin = tid + v * 256;
            int r = lin >> 2, c4 = (lin & 3) << 2;
            As[buf][c4 + 0][r] = pa[v].x; As[buf][c4 + 1][r] = pa[v].y;
            As[buf][c4 + 2][r] = pa[v].z; As[buf][c4 + 3][r] = pa[v].w;
            Bs[buf][c4 + 0][r] = pb[v].x; Bs[buf][c4 + 1][r] = pb[v].y;
            Bs[buf][c4 + 2][r] = pb[v].z; Bs[buf][c4 + 3][r] = pb[v].w;
        }
    };

    gload(0); sstore(0); __syncthreads();

    for (int kt = 0; kt < NKT; kt++) {
        int cur = kt & 1;
        bool more = (kt + 1 < NKT);
        if (more) gload(kt + 1);
        #pragma unroll
        for (int k = 0; k < TK; k++) {
            float4 a0 = *(const float4*)&As[cur][k][m0];
            float4 a1 = *(const float4*)&As[cur][k][m0 + 4];
            float4 b0 = *(const float4*)&Bs[cur][k][n0];
            float4 b1 = *(const float4*)&Bs[cur][k][n0 + 4];
            float av[8] = {a0.x, a0.y, a0.z, a0.w, a1.x, a1.y, a1.z, a1.w};
            float bv[8] = {b0.x, b0.y, b0.z, b0.w, b1.x, b1.y, b1.z, b1.w};
            #pragma unroll
            for (int i = 0; i < 8; i++)
                #pragma unroll
                for (int j = 0; j < 8; j++) acc[i][j] += av[i] * bv[j];
        }
        if (more) sstore(cur ^ 1);
        __syncthreads();
    }

    // epilogue: d2 = pn + ln - 2*dot, per-column min over m (packed with lib idx)
    float ln_r[8], pn_s[8];
    #pragma unroll
    for (int i = 0; i < 8; i++) {
        int gm = bm + m0 + i;
        ln_r[i] = (gm < MLIB) ? g_ln[gm] : 0.f;
    }
    #pragma unroll
    for (int j = 0; j < 8; j++) pn_s[j] = g_pn[bn + n0 + j];

    #pragma unroll
    for (int j = 0; j < 8; j++) {
        unsigned long long best = ~0ull;
        #pragma unroll
        for (int i = 0; i < 8; i++) {
            int gm = bm + m0 + i;
            if (gm < MLIB) {
                float d2 = fmaxf(pn_s[j] + ln_r[i] - 2.f * acc[i][j], 0.f);
                unsigned long long p = ((unsigned long long)__float_as_uint(d2) << 32)
                                       | (unsigned int)gm;
                best = (p < best) ? p : best;
            }
        }
        atomicMin(&colmin[n0 + j], best);
    }
    __syncthreads();
    if (tid < TN) {
        int gn = bn + tid;
        if (gn < NPATCH && colmin[tid] != ~0ull) atomicMin(&g_minpack[gn], colmin[tid]);
    }
}

// ---------------- K4: select s_idx (argmax of min dist), copy m_test_star / m_star ----------------
__global__ void k_select(const float* __restrict__ lib) {
    __shared__ int sidx_s, midx_s;
    if (threadIdx.x == 0) {
        float best = -1.f; int bi = 0;
        for (int i = 0; i < NPATCH; i++) {
            unsigned long long p = g_minpack[i];
            float dist = sqrtf(__uint_as_float((unsigned int)(p >> 32)));
            if (dist > best) { best = dist; bi = i; }
        }
        unsigned long long p = g_minpack[bi];
        int mi = (int)(unsigned int)(p & 0xffffffffu);
        g_scal.s_idx = bi; g_scal.s_star = best; g_scal.m_idx = mi; g_scal.msn = g_ln[mi];
        sidx_s = bi; midx_s = mi;
    }
    __syncthreads();
    for (int c = threadIdx.x; c < DDIM; c += blockDim.x) {
        g_mt[c] = g_patchN[sidx_s * DDIM + c];
        g_ms[c] = lib[(size_t)midx_s * DDIM + c];
    }
}

// ---------------- K5: d_star2[j] = ln[j] + ||m_star||^2 - 2 lib_j . m_star ----------------
__global__ void k_dstar(const float* __restrict__ lib) {
    __shared__ float ms[DDIM];
    for (int c = threadIdx.x; c < DDIM; c += 256) ms[c] = g_ms[c];
    __syncthreads();
    int row  = blockIdx.x * 8 + (threadIdx.x >> 5);
    int lane = threadIdx.x & 31;
    const float* p = lib + (size_t)row * DDIM;
    float s = 0.f;
    for (int c = lane; c < DDIM; c += 32) s += p[c] * ms[c];
    #pragma unroll
    for (int o = 16; o > 0; o >>= 1) s += __shfl_down_sync(0xffffffffu, s, o);
    if (lane == 0) g_dstar[row] = fmaxf(g_ln[row] + g_scal.msn - 2.f * s, 0.f);
}

// ---------------- K6: global top-5 smallest d_star (ties -> lowest index) ----------------
__device__ __forceinline__ void merge5(unsigned long long* a, const unsigned long long* b) {
    unsigned long long o[5]; int ia = 0, ib = 0;
    #pragma unroll
    for (int k = 0; k < 5; k++) {
        unsigned long long va = a[ia], vb = b[ib];
        if (va <= vb) { o[k] = va; ia++; } else { o[k] = vb; ib++; }
    }
    #pragma unroll
    for (int k = 0; k < 5; k++) a[k] = o[k];
}

__global__ void k_top5() {
    __shared__ unsigned long long L[1024 * 5];   // 40 KB
    int tid = threadIdx.x;
    unsigned long long arr[5];
    #pragma unroll
    for (int k = 0; k < 5; k++) arr[k] = ~0ull;
    for (int j = tid; j < MLIB; j += 1024) {
        unsigned long long p = ((unsigned long long)__float_as_uint(g_dstar[j]) << 32)
                               | (unsigned int)j;
        if (p < arr[4]) {
            arr[4] = p;
            #pragma unroll
            for (int k = 4; k > 0; k--)
                if (arr[k] < arr[k - 1]) { unsigned long long t = arr[k]; arr[k] = arr[k - 1]; arr[k - 1] = t; }
        }
    }
    #pragma unroll
    for (int k = 0; k < 5; k++) L[tid * 5 + k] = arr[k];
    __syncthreads();
    for (int s = 512; s > 0; s >>= 1) {
        if (tid < s) merge5(&L[tid * 5], &L[(tid + s) * 5]);
        __syncthreads();
    }
    if (tid == 0) {
        #pragma unroll
        for (int k = 0; k < 5; k++) g_nn[k] = (int)(unsigned int)(L[k] & 0xffffffffu);
    }
}

// ---------------- K7: final scalar s ----------------
__global__ void k_final(const float* __restrict__ lib, float* __restrict__ out) {
    __shared__ float res[6];
    int w = threadIdx.x >> 5, lane = threadIdx.x & 31;   // 192 threads, 6 warps
    float part = 0.f;
    if (w < KTOP) {
        const float* p = lib + (size_t)g_nn[w] * DDIM;
        for (int c = lane; c < DDIM; c += 32) { float d = g_mt[c] - p[c]; part += d * d; }
    } else {
        for (int c = lane; c < DDIM; c += 32) { float d = g_mt[c] - g_ms[c]; part += d * d; }
    }
    #pragma unroll
    for (int o = 16; o > 0; o >>= 1) part += __shfl_down_sync(0xffffffffu, part, o);
    if (lane == 0) res[w] = sqrtf(part);
    __syncthreads();
    if (threadIdx.x == 0) {
        float num = expf(res[5]);
        float den = 0.f;
        #pragma unroll
        for (int k = 0; k < KTOP; k++) den += expf(res[k]);
        out[0] = (1.f - num / den) * g_scal.s_star;
    }
}

// ---------------- K8: bilinear resize 26x26 -> 224x224 (half-pixel, clamp) ----------------
__device__ __forceinline__ float minval_at(int y, int x) {
    return sqrtf(__uint_as_float((unsigned int)(g_minpack[y * HWDIM + x] >> 32)));
}

__global__ void k_resize() {
    int idx = blockIdx.x * 256 + threadIdx.x;
    if (idx >= IMG * IMG) return;
    int oy = idx / IMG, ox = idx % IMG;
    const float sc = (float)HWDIM / (float)IMG;
    float fy = fmaxf((oy + 0.5f) * sc - 0.5f, 0.f);
    float fx = fmaxf((ox + 0.5f) * sc - 0.5f, 0.f);
    int y0 = min((int)fy, HWDIM - 1), x0 = min((int)fx, HWDIM - 1);
    float wy = fy - y0, wx = fx - x0;
    int y1 = min(y0 + 1, HWDIM - 1), x1 = min(x0 + 1, HWDIM - 1);
    float v00 = minval_at(y0, x0), v01 = minval_at(y0, x1);
    float v10 = minval_at(y1, x0), v11 = minval_at(y1, x1);
    g_map1[idx] = (1.f - wy) * ((1.f - wx) * v00 + wx * v01)
                +        wy  * ((1.f - wx) * v10 + wx * v11);
}

// ---------------- K9/K10: separable gaussian blur (reflect padding) ----------------
__device__ __forceinline__ int reflect_idx(int i) {
    if (i < 0) i = -i;
    if (i > IMG - 1) i = 2 * (IMG - 1) - i;
    return i;
}

__global__ void k_blurV() {   // vertical pass (matches kh applied first)
    int idx = blockIdx.x * 256 + threadIdx.x;
    if (idx >= IMG * IMG) return;
    int oy = idx / IMG, ox = idx % IMG;
    float wsum = 0.f, acc = 0.f;
    #pragma unroll
    for (int j = -KRAD; j <= KRAD; j++) {
        float w = expf(-0.5f * ((float)j / SIGMA) * ((float)j / SIGMA));
        wsum += w;
        acc += w * g_map1[reflect_idx(oy + j) * IMG + ox];
    }
    g_map2[idx] = acc / wsum;
}

__global__ void k_blurH(float* __restrict__ out) {
    int idx = blockIdx.x * 256 + threadIdx.x;
    if (idx >= IMG * IMG) return;
    int oy = idx / IMG, ox = idx % IMG;
    float wsum = 0.f, acc = 0.f;
    #pragma unroll
    for (int j = -KRAD; j <= KRAD; j++) {
        float w = expf(-0.5f * ((float)j / SIGMA) * ((float)j / SIGMA));
        wsum += w;
        acc += w * g_map2[oy * IMG + reflect_idx(ox + j)];
    }
    out[1 + idx] = acc / wsum;   // out[0] = s, out[1..] = s_map (224x224 row-major)
}

// ---------------- launch ----------------
extern "C" void kernel_launch(void* const* d_in, const int* in_sizes, int n_in,
                              void* d_out, int out_size) {
    const float* patch = (const float*)d_in[0];       // [676, 384]
    const float* lib   = (const float*)d_in[1];       // [200000, 384]
    float* out = (float*)d_out;                       // [1 + 224*224]

    k_norm<<<NPAD, 128>>>(patch);
    k_ln<<<MLIB / 8, 256>>>(lib);
    {
        dim3 grid(NPAD / TN, (MLIB + TM - 1) / TM);   // (6, 1563); x fast -> L2 reuse of lib tile
        k_gemm<<<grid, 256>>>(lib);
    }
    k_select<<<1, 384>>>(lib);
    k_dstar<<<MLIB / 8, 256>>>(lib);
    k_top5<<<1, 1024>>>();
    k_final<<<1, 192>>>(lib, out);
    k_resize<<<(IMG * IMG + 255) / 256, 256>>>();
    k_blurV<<<(IMG * IMG + 255) / 256, 256>>>();
    k_blurH<<<(IMG * IMG + 255) / 256, 256>>>(out);
}

// round 2
// speedup vs baseline: 1.5853x; 1.5853x over previous
#include <cuda_runtime.h>
#include <cstdint>

// ---------------- problem constants ----------------
#define MLIB   200000
#define NPATCH 676
#define NPAD   768
#define DDIM   384
#define IMG    224
#define HWDIM  26
#define KTOP   5
#define SIGMA  4.0f
#define KRAD   16          // (KS-1)/2, KS=33

// ---------------- device scratch (no allocations allowed) ----------------
__device__ __align__(16) float g_patchN[NPAD * DDIM];   // normalized patch, zero-padded rows
__device__ float g_pn[NPAD];                            // ||patchN_row||^2 (== pn in reference)
__device__ float g_ln[MLIB];                            // ||lib_row||^2
__device__ unsigned long long g_minpack[NPATCH];        // (d2_bits<<32)|lib_idx  per patch
__device__ float g_dstar[MLIB];                         // d2 from m_star to lib
__device__ int   g_nn[KTOP];
struct Scal { int s_idx; float s_star; int m_idx; float msn; };
__device__ Scal  g_scal;
__device__ float g_mt[DDIM];                            // m_test_star
__device__ float g_ms[DDIM];                            // m_star
__device__ float g_map1[IMG * IMG];
__device__ float g_map2[IMG * IMG];

// ---------------- K1: init + L2-normalize patch rows, compute pn ----------------
__global__ void k_norm(const float* __restrict__ patch) {
    int row = blockIdx.x;          // 0..767
    int t = threadIdx.x;           // 128 threads
    __shared__ float red[128];

    if (t == 0 && row < NPATCH) g_minpack[row] = ~0ull;

    float s = 0.f;
    if (row < NPATCH) {
        for (int c = t; c < DDIM; c += 128) { float v = patch[row * DDIM + c]; s += v * v; }
    }
    red[t] = s; __syncthreads();
    for (int st = 64; st > 0; st >>= 1) { if (t < st) red[t] += red[t + st]; __syncthreads(); }
    float inv = 0.f;
    if (row < NPATCH) { float n = sqrtf(red[0]); inv = 1.f / fmaxf(n, 1e-12f); }
    __syncthreads();

    float s2 = 0.f;
    for (int c = t; c < DDIM; c += 128) {
        float y = (row < NPATCH) ? patch[row * DDIM + c] * inv : 0.f;
        g_patchN[row * DDIM + c] = y;
        s2 += y * y;
    }
    red[t] = s2; __syncthreads();
    for (int st = 64; st > 0; st >>= 1) { if (t < st) red[t] += red[t + st]; __syncthreads(); }
    if (t == 0) g_pn[row] = (row < NPATCH) ? red[0] : 0.f;
}

// ---------------- K2: ln[j] = ||lib_j||^2 (warp per row) ----------------
__global__ void k_ln(const float* __restrict__ lib) {
    int row  = blockIdx.x * 8 + (threadIdx.x >> 5);   // grid 25000 x 256 -> 200000 rows
    int lane = threadIdx.x & 31;
    const float* p = lib + (size_t)row * DDIM;
    float s = 0.f;
    for (int c = lane; c < DDIM; c += 32) { float v = p[c]; s += v * v; }
    #pragma unroll
    for (int o = 16; o > 0; o >>= 1) s += __shfl_down_sync(0xffffffffu, s, o);
    if (lane == 0) g_ln[row] = s;
}

// ---------------- K3: fused distance GEMM + per-patch min/argmin ----------------
#define TM 128
#define TN 128
#define TK 16
#define NKT (DDIM / TK)   // 24

__global__ __launch_bounds__(256, 2) void k_gemm(const float* __restrict__ lib) {
    __shared__ __align__(16) float As[2][TK][TM];
    __shared__ __align__(16) float Bs[2][TK][TN];
    __shared__ unsigned long long colmin[TN];

    const int bm = blockIdx.y * TM;    // lib chunk
    const int bn = blockIdx.x * TN;    // patch chunk (padded to 768)
    const int tid = threadIdx.x;
    if (tid < TN) colmin[tid] = ~0ull;

    const int m0 = (tid >> 4) << 3;
    const int n0 = (tid & 15) << 3;

    float acc[8][8];
    #pragma unroll
    for (int i = 0; i < 8; i++)
        #pragma unroll
        for (int j = 0; j < 8; j++) acc[i][j] = 0.f;

    float4 pa[2], pb[2];

    auto gload = [&](int kt) {
        int k0 = kt * TK;
        #pragma unroll
        for (int v = 0; v < 2; v++) {
            int lin = tid + v * 256;              // 512 float4 slots per operand
            int r = lin >> 2, c4 = (lin & 3) << 2;
            int gm = bm + r;
            float4 a = make_float4(0.f, 0.f, 0.f, 0.f);
            if (gm < MLIB) a = *(const float4*)(lib + (size_t)gm * DDIM + k0 + c4);
            pa[v] = a;
            pb[v] = *(const float4*)(g_patchN + (size_t)(bn + r) * DDIM + k0 + c4);
        }
    };
    auto sstore = [&](int buf) {
        #pragma unroll
        for (int v = 0; v < 2; v++) {
            int lin = tid + v * 256;
            int r = lin >> 2, c4 = (lin & 3) << 2;
            As[buf][c4 + 0][r] = pa[v].x; As[buf][c4 + 1][r] = pa[v].y;
            As[buf][c4 + 2][r] = pa[v].z; As[buf][c4 + 3][r] = pa[v].w;
            Bs[buf][c4 + 0][r] = pb[v].x; Bs[buf][c4 + 1][r] = pb[v].y;
            Bs[buf][c4 + 2][r] = pb[v].z; Bs[buf][c4 + 3][r] = pb[v].w;
        }
    };

    gload(0); sstore(0); __syncthreads();

    for (int kt = 0; kt < NKT; kt++) {
        int cur = kt & 1;
        bool more = (kt + 1 < NKT);
        if (more) gload(kt + 1);
        #pragma unroll
        for (int k = 0; k < TK; k++) {
            float4 a0 = *(const float4*)&As[cur][k][m0];
            float4 a1 = *(const float4*)&As[cur][k][m0 + 4];
            float4 b0 = *(const float4*)&Bs[cur][k][n0];
            float4 b1 = *(const float4*)&Bs[cur][k][n0 + 4];
            float av[8] = {a0.x, a0.y, a0.z, a0.w, a1.x, a1.y, a1.z, a1.w};
            float bv[8] = {b0.x, b0.y, b0.z, b0.w, b1.x, b1.y, b1.z, b1.w};
            #pragma unroll
            for (int i = 0; i < 8; i++)
                #pragma unroll
                for (int j = 0; j < 8; j++) acc[i][j] += av[i] * bv[j];
        }
        if (more) sstore(cur ^ 1);
        __syncthreads();
    }

    // epilogue: d2 = pn + ln - 2*dot, per-column min over m (packed with lib idx)
    float ln_r[8], pn_s[8];
    #pragma unroll
    for (int i = 0; i < 8; i++) {
        int gm = bm + m0 + i;
        ln_r[i] = (gm < MLIB) ? g_ln[gm] : 0.f;
    }
    #pragma unroll
    for (int j = 0; j < 8; j++) pn_s[j] = g_pn[bn + n0 + j];

    #pragma unroll
    for (int j = 0; j < 8; j++) {
        unsigned long long best = ~0ull;
        #pragma unroll
        for (int i = 0; i < 8; i++) {
            int gm = bm + m0 + i;
            if (gm < MLIB) {
                float d2 = fmaxf(pn_s[j] + ln_r[i] - 2.f * acc[i][j], 0.f);
                unsigned long long p = ((unsigned long long)__float_as_uint(d2) << 32)
                                       | (unsigned int)gm;
                best = (p < best) ? p : best;
            }
        }
        atomicMin(&colmin[n0 + j], best);
    }
    __syncthreads();
    if (tid < TN) {
        int gn = bn + tid;
        if (gn < NPATCH && colmin[tid] != ~0ull) atomicMin(&g_minpack[gn], colmin[tid]);
    }
}

// ---------------- K4: select s_idx (argmax of min dist), copy m_test_star / m_star ----------------
__global__ void k_select(const float* __restrict__ lib) {
    __shared__ int sidx_s, midx_s;
    if (threadIdx.x == 0) {
        float best = -1.f; int bi = 0;
        for (int i = 0; i < NPATCH; i++) {
            unsigned long long p = g_minpack[i];
            float dist = sqrtf(__uint_as_float((unsigned int)(p >> 32)));
            if (dist > best) { best = dist; bi = i; }
        }
        unsigned long long p = g_minpack[bi];
        int mi = (int)(unsigned int)(p & 0xffffffffu);
        g_scal.s_idx = bi; g_scal.s_star = best; g_scal.m_idx = mi; g_scal.msn = g_ln[mi];
        sidx_s = bi; midx_s = mi;
    }
    __syncthreads();
    for (int c = threadIdx.x; c < DDIM; c += blockDim.x) {
        g_mt[c] = g_patchN[sidx_s * DDIM + c];
        g_ms[c] = lib[(size_t)midx_s * DDIM + c];
    }
}

// ---------------- K5: d_star2[j] = ln[j] + ||m_star||^2 - 2 lib_j . m_star ----------------
__global__ void k_dstar(const float* __restrict__ lib) {
    __shared__ float ms[DDIM];
    for (int c = threadIdx.x; c < DDIM; c += 256) ms[c] = g_ms[c];
    __syncthreads();
    int row  = blockIdx.x * 8 + (threadIdx.x >> 5);
    int lane = threadIdx.x & 31;
    const float* p = lib + (size_t)row * DDIM;
    float s = 0.f;
    for (int c = lane; c < DDIM; c += 32) s += p[c] * ms[c];
    #pragma unroll
    for (int o = 16; o > 0; o >>= 1) s += __shfl_down_sync(0xffffffffu, s, o);
    if (lane == 0) g_dstar[row] = fmaxf(g_ln[row] + g_scal.msn - 2.f * s, 0.f);
}

// ---------------- K6: global top-5 smallest d_star (ties -> lowest index) ----------------
__device__ __forceinline__ void merge5(unsigned long long* a, const unsigned long long* b) {
    unsigned long long o[5]; int ia = 0, ib = 0;
    #pragma unroll
    for (int k = 0; k < 5; k++) {
        unsigned long long va = a[ia], vb = b[ib];
        if (va <= vb) { o[k] = va; ia++; } else { o[k] = vb; ib++; }
    }
    #pragma unroll
    for (int k = 0; k < 5; k++) a[k] = o[k];
}

__global__ void k_top5() {
    __shared__ unsigned long long L[1024 * 5];   // 40 KB
    int tid = threadIdx.x;
    unsigned long long arr[5];
    #pragma unroll
    for (int k = 0; k < 5; k++) arr[k] = ~0ull;
    for (int j = tid; j < MLIB; j += 1024) {
        unsigned long long p = ((unsigned long long)__float_as_uint(g_dstar[j]) << 32)
                               | (unsigned int)j;
        if (p < arr[4]) {
            arr[4] = p;
            #pragma unroll
            for (int k = 4; k > 0; k--)
                if (arr[k] < arr[k - 1]) { unsigned long long t = arr[k]; arr[k] = arr[k - 1]; arr[k - 1] = t; }
        }
    }
    #pragma unroll
    for (int k = 0; k < 5; k++) L[tid * 5 + k] = arr[k];
    __syncthreads();
    for (int s = 512; s > 0; s >>= 1) {
        if (tid < s) merge5(&L[tid * 5], &L[(tid + s) * 5]);
        __syncthreads();
    }
    if (tid == 0) {
        #pragma unroll
        for (int k = 0; k < 5; k++) g_nn[k] = (int)(unsigned int)(L[k] & 0xffffffffu);
    }
}

// ---------------- K7: final scalar s ----------------
__global__ void k_final(const float* __restrict__ lib, float* __restrict__ out) {
    __shared__ float res[6];
    int w = threadIdx.x >> 5, lane = threadIdx.x & 31;   // 192 threads, 6 warps
    float part = 0.f;
    if (w < KTOP) {
        const float* p = lib + (size_t)g_nn[w] * DDIM;
        for (int c = lane; c < DDIM; c += 32) { float d = g_mt[c] - p[c]; part += d * d; }
    } else {
        for (int c = lane; c < DDIM; c += 32) { float d = g_mt[c] - g_ms[c]; part += d * d; }
    }
    #pragma unroll
    for (int o = 16; o > 0; o >>= 1) part += __shfl_down_sync(0xffffffffu, part, o);
    if (lane == 0) res[w] = sqrtf(part);
    __syncthreads();
    if (threadIdx.x == 0) {
        float num = expf(res[5]);
        float den = 0.f;
        #pragma unroll
        for (int k = 0; k < KTOP; k++) den += expf(res[k]);
        out[0] = (1.f - num / den) * g_scal.s_star;
    }
}

// ---------------- K8: bilinear resize 26x26 -> 224x224 (half-pixel, clamp) ----------------
__device__ __forceinline__ float minval_at(int y, int x) {
    return sqrtf(__uint_as_float((unsigned int)(g_minpack[y * HWDIM + x] >> 32)));
}

__global__ void k_resize() {
    int idx = blockIdx.x * 256 + threadIdx.x;
    if (idx >= IMG * IMG) return;
    int oy = idx / IMG, ox = idx % IMG;
    const float sc = (float)HWDIM / (float)IMG;
    float fy = fmaxf((oy + 0.5f) * sc - 0.5f, 0.f);
    float fx = fmaxf((ox + 0.5f) * sc - 0.5f, 0.f);
    int y0 = min((int)fy, HWDIM - 1), x0 = min((int)fx, HWDIM - 1);
    float wy = fy - y0, wx = fx - x0;
    int y1 = min(y0 + 1, HWDIM - 1), x1 = min(x0 + 1, HWDIM - 1);
    float v00 = minval_at(y0, x0), v01 = minval_at(y0, x1);
    float v10 = minval_at(y1, x0), v11 = minval_at(y1, x1);
    g_map1[idx] = (1.f - wy) * ((1.f - wx) * v00 + wx * v01)
                +        wy  * ((1.f - wx) * v10 + wx * v11);
}

// ---------------- K9/K10: separable gaussian blur (reflect padding) ----------------
__device__ __forceinline__ int reflect_idx(int i) {
    if (i < 0) i = -i;
    if (i > IMG - 1) i = 2 * (IMG - 1) - i;
    return i;
}

__global__ void k_blurV() {   // vertical pass (matches kh applied first)
    int idx = blockIdx.x * 256 + threadIdx.x;
    if (idx >= IMG * IMG) return;
    int oy = idx / IMG, ox = idx % IMG;
    float wsum = 0.f, acc = 0.f;
    #pragma unroll
    for (int j = -KRAD; j <= KRAD; j++) {
        float w = expf(-0.5f * ((float)j / SIGMA) * ((float)j / SIGMA));
        wsum += w;
        acc += w * g_map1[reflect_idx(oy + j) * IMG + ox];
    }
    g_map2[idx] = acc / wsum;
}

__global__ void k_blurH(float* __restrict__ out) {
    int idx = blockIdx.x * 256 + threadIdx.x;
    if (idx >= IMG * IMG) return;
    int oy = idx / IMG, ox = idx % IMG;
    float wsum = 0.f, acc = 0.f;
    #pragma unroll
    for (int j = -KRAD; j <= KRAD; j++) {
        float w = expf(-0.5f * ((float)j / SIGMA) * ((float)j / SIGMA));
        wsum += w;
        acc += w * g_map2[oy * IMG + reflect_idx(ox + j)];
    }
    out[1 + idx] = acc / wsum;   // out[0] = s, out[1..] = s_map (224x224 row-major)
}

// ---------------- launch ----------------
extern "C" void kernel_launch(void* const* d_in, const int* in_sizes, int n_in,
                              void* d_out, int out_size) {
    const float* patch = (const float*)d_in[0];       // [676, 384]
    const float* lib   = (const float*)d_in[1];       // [200000, 384]
    float* out = (float*)d_out;                       // [1 + 224*224]

    k_norm<<<NPAD, 128>>>(patch);
    k_ln<<<MLIB / 8, 256>>>(lib);
    {
        dim3 grid(NPAD / TN, (MLIB + TM - 1) / TM);   // (6, 1563); x fast -> L2 reuse of lib tile
        k_gemm<<<grid, 256>>>(lib);
    }
    k_select<<<1, 384>>>(lib);
    k_dstar<<<MLIB / 8, 256>>>(lib);
    k_top5<<<1, 1024>>>();
    k_final<<<1, 192>>>(lib, out);
    k_resize<<<(IMG * IMG + 255) / 256, 256>>>();
    k_blurV<<<(IMG * IMG + 255) / 256, 256>>>();
    k_blurH<<<(IMG * IMG + 255) / 256, 256>>>(out);
}

// round 5
// speedup vs baseline: 6.7710x; 4.2712x over previous
#include <cuda_runtime.h>
#include <cuda_fp16.h>
#include <cstdint>

#define MLIB   200000
#define MPAD   200064          // 1563 * 128
#define NPATCH 676
#define NPAD   768
#define DDIM   384
#define IMG    224
#define HWDIM  26
#define KTOP   5
#define SIGMA  4.0f
#define KRAD   16

// GEMM tiling
#define GTM 128
#define GTN 128
#define NKC 12                 // 384 / 32
#define ROWB 80                // 32 fp16 = 64B, padded to 80B (conflict-free ldmatrix)
#define OPB (128 * ROWB)       // 10240 per operand per stage
#define STG (2 * OPB)          // 20480
#define SMEMG (3 * STG)        // 61440

// ---------------- device scratch ----------------
__device__ __align__(16) __half g_libH[(size_t)MPAD * DDIM];   // fp16 lib (zero-padded rows)
__device__ __align__(16) __half g_patH[(size_t)NPAD * DDIM];   // fp16 normalized patches
__device__ __align__(16) float g_patchN[NPAD * DDIM];
__device__ float g_pn[NPAD];
__device__ float g_ln[MLIB];
__device__ unsigned long long g_minpack[NPATCH];
__device__ float g_dstar[MLIB];
__device__ int   g_nn[KTOP];
struct Scal { int s_idx; float s_star; int m_idx; float msn; };
__device__ Scal  g_scal;
__device__ float g_mt[DDIM];
__device__ float g_ms[DDIM];
__device__ float g_map1[IMG * IMG];
__device__ float g_map2[IMG * IMG];

// ---------------- helpers ----------------
__device__ __forceinline__ uint32_t smem_u32(const void* p) {
    uint32_t a;
    asm("{ .reg .u64 t; cvta.to.shared.u64 t, %1; cvt.u32.u64 %0, t; }" : "=r"(a) : "l"(p));
    return a;
}
__device__ __forceinline__ void cp16(uint32_t dst, const void* src) {
    asm volatile("cp.async.cg.shared.global [%0], [%1], 16;" :: "r"(dst), "l"(src));
}
__device__ __forceinline__ void ldsm4(uint32_t* r, uint32_t addr) {
    asm volatile("ldmatrix.sync.aligned.m8n8.x4.shared.b16 {%0,%1,%2,%3}, [%4];"
                 : "=r"(r[0]), "=r"(r[1]), "=r"(r[2]), "=r"(r[3]) : "r"(addr));
}
__device__ __forceinline__ void mma16816(float* c, const uint32_t* a, uint32_t b0, uint32_t b1) {
    asm volatile("mma.sync.aligned.m16n8k16.row.col.f32.f16.f16.f32 "
                 "{%0,%1,%2,%3}, {%4,%5,%6,%7}, {%8,%9}, {%0,%1,%2,%3};"
                 : "+f"(c[0]), "+f"(c[1]), "+f"(c[2]), "+f"(c[3])
                 : "r"(a[0]), "r"(a[1]), "r"(a[2]), "r"(a[3]), "r"(b0), "r"(b1));
}

// ---------------- K1: normalize patches ----------------
__global__ void k_norm(const float* __restrict__ patch) {
    int row = blockIdx.x, t = threadIdx.x;   // 768 x 128
    __shared__ float red[128];
    if (t == 0 && row < NPATCH) g_minpack[row] = ~0ull;
    float s = 0.f;
    if (row < NPATCH)
        for (int c = t; c < DDIM; c += 128) { float v = patch[row * DDIM + c]; s += v * v; }
    red[t] = s; __syncthreads();
    for (int st = 64; st > 0; st >>= 1) { if (t < st) red[t] += red[t + st]; __syncthreads(); }
    float inv = 0.f;
    if (row < NPATCH) inv = 1.f / fmaxf(sqrtf(red[0]), 1e-12f);
    __syncthreads();
    float s2 = 0.f;
    for (int c = t; c < DDIM; c += 128) {
        float y = (row < NPATCH) ? patch[row * DDIM + c] * inv : 0.f;
        g_patchN[row * DDIM + c] = y;
        s2 += y * y;
    }
    red[t] = s2; __syncthreads();
    for (int st = 64; st > 0; st >>= 1) { if (t < st) red[t] += red[t + st]; __syncthreads(); }
    if (t == 0) g_pn[row] = (row < NPATCH) ? red[0] : 0.f;
}

// ---------------- K2: lib -> fp16 + ln ----------------
__global__ void k_split(const float* __restrict__ lib) {   // grid MPAD/8 x 256
    int row = blockIdx.x * 8 + (threadIdx.x >> 5);
    int lane = threadIdx.x & 31;
    bool v = row < MLIB;
    float ss = 0.f;
    __half2* dst = (__half2*)(g_libH + (size_t)row * DDIM);
    #pragma unroll
    for (int i = 0; i < 6; i++) {
        float2 x = make_float2(0.f, 0.f);
        if (v) x = *(const float2*)(lib + (size_t)row * DDIM + i * 64 + lane * 2);
        ss += x.x * x.x + x.y * x.y;
        dst[i * 32 + lane] = __floats2half2_rn(x.x, x.y);
    }
    #pragma unroll
    for (int o = 16; o > 0; o >>= 1) ss += __shfl_down_sync(0xffffffffu, ss, o);
    if (lane == 0 && v) g_ln[row] = ss;
}

// ---------------- K3: patches -> fp16 ----------------
__global__ void k_splitP() {                               // grid 96 x 256
    int row = blockIdx.x * 8 + (threadIdx.x >> 5);
    int lane = threadIdx.x & 31;
    __half2* dst = (__half2*)(g_patH + (size_t)row * DDIM);
    #pragma unroll
    for (int i = 0; i < 6; i++) {
        float2 x = *(const float2*)(g_patchN + (size_t)row * DDIM + i * 64 + lane * 2);
        dst[i * 32 + lane] = __floats2half2_rn(x.x, x.y);
    }
}

// ---------------- K4: HMMA GEMM + fused per-patch min ----------------
__global__ void __launch_bounds__(256) k_gemm() {
    extern __shared__ __align__(16) unsigned char dyn[];
    __shared__ float s_ln[GTN];
    __shared__ unsigned long long s_min[GTM];

    const int tid = threadIdx.x;
    const int w = tid >> 5, lane = tid & 31;
    const int wm = w & 3, wn = w >> 2;        // 4 m-warps x 2 n-warps
    const int bp = blockIdx.x * GTM;          // patch base (0..640)
    const int bm = blockIdx.y * GTN;          // lib base
    const uint32_t sb = smem_u32(dyn);

    if (tid < GTN) {
        int gcol = bm + tid;
        s_ln[tid] = (gcol < MLIB) ? g_ln[gcol] : __int_as_float(0x7f800000);
        s_min[tid] = ~0ull;
    }

    auto load_stage = [&](int kc, int st) {
        #pragma unroll
        for (int i = 0; i < 2; i++) {
            int q = tid + i * 256;
            int r = q >> 2, c = q & 3;
            cp16(sb + st * STG + r * ROWB + c * 16,
                 (const char*)g_patH + ((size_t)(bp + r) * DDIM + kc * 32) * 2 + c * 16);
            cp16(sb + st * STG + OPB + r * ROWB + c * 16,
                 (const char*)g_libH + ((size_t)(bm + r) * DDIM + kc * 32) * 2 + c * 16);
        }
        asm volatile("cp.async.commit_group;");
    };

    float acc[2][8][4];
    #pragma unroll
    for (int mt = 0; mt < 2; mt++)
        #pragma unroll
        for (int nt = 0; nt < 8; nt++)
            #pragma unroll
            for (int e = 0; e < 4; e++) acc[mt][nt][e] = 0.f;

    load_stage(0, 0);
    load_stage(1, 1);

    for (int kc = 0; kc < NKC; kc++) {
        if (kc < NKC - 2) {
            load_stage(kc + 2, (kc + 2) % 3);
            asm volatile("cp.async.wait_group 2;");
        } else if (kc == NKC - 2) {
            asm volatile("cp.async.wait_group 1;");
        } else {
            asm volatile("cp.async.wait_group 0;");
        }
        __syncthreads();

        const int st = kc % 3;
        const uint32_t abase = sb + st * STG;
        const uint32_t bbase = abase + OPB;
        #pragma unroll
        for (int ks = 0; ks < 2; ks++) {
            uint32_t a[2][4];
            #pragma unroll
            for (int mt = 0; mt < 2; mt++) {
                uint32_t addr = abase + (wm * 32 + mt * 16 + (lane & 15)) * ROWB
                              + ks * 32 + (lane >> 4) * 16;
                ldsm4(a[mt], addr);
            }
            uint32_t b[4][4];
            #pragma unroll
            for (int p = 0; p < 4; p++) {
                int rowl = wn * 64 + p * 16 + (lane & 7) + ((lane >> 4) << 3);
                uint32_t addr = bbase + rowl * ROWB + ks * 32 + ((lane >> 3) & 1) * 16;
                ldsm4(b[p], addr);
            }
            #pragma unroll
            for (int mt = 0; mt < 2; mt++)
                #pragma unroll
                for (int p = 0; p < 4; p++) {
                    mma16816(acc[mt][2 * p + 0], a[mt], b[p][0], b[p][1]);
                    mma16816(acc[mt][2 * p + 1], a[mt], b[p][2], b[p][3]);
                }
        }
        __syncthreads();
    }

    // epilogue: d2 = pn + ln - 2*dot, packed min over this thread's columns
    const int tq = lane >> 2, tr = lane & 3;
    #pragma unroll
    for (int mt = 0; mt < 2; mt++) {
        int lr0 = wm * 32 + mt * 16 + tq;
        float pn0 = g_pn[bp + lr0];
        float pn1 = g_pn[bp + lr0 + 8];
        unsigned long long best0 = ~0ull, best1 = ~0ull;
        #pragma unroll
        for (int nt = 0; nt < 8; nt++) {
            int lc = wn * 64 + nt * 8 + tr * 2;
            unsigned int gc0 = (unsigned int)(bm + lc);
            float ln0 = s_ln[lc], ln1 = s_ln[lc + 1];
            const float* c = acc[mt][nt];
            float d2;
            unsigned long long p;
            d2 = fmaxf(pn0 + ln0 - 2.f * c[0], 0.f);
            p = ((unsigned long long)__float_as_uint(d2) << 32) | gc0;
            best0 = (p < best0) ? p : best0;
            d2 = fmaxf(pn0 + ln1 - 2.f * c[1], 0.f);
            p = ((unsigned long long)__float_as_uint(d2) << 32) | (gc0 + 1);
            best0 = (p < best0) ? p : best0;
            d2 = fmaxf(pn1 + ln0 - 2.f * c[2], 0.f);
            p = ((unsigned long long)__float_as_uint(d2) << 32) | gc0;
            best1 = (p < best1) ? p : best1;
            d2 = fmaxf(pn1 + ln1 - 2.f * c[3], 0.f);
            p = ((unsigned long long)__float_as_uint(d2) << 32) | (gc0 + 1);
            best1 = (p < best1) ? p : best1;
        }
        atomicMin(&s_min[lr0], best0);
        atomicMin(&s_min[lr0 + 8], best1);
    }
    __syncthreads();
    if (tid < GTM) {
        int gp = bp + tid;
        if (gp < NPATCH) atomicMin(&g_minpack[gp], s_min[tid]);
    }
}

// ---------------- K5: parallel select ----------------
__global__ void k_select(const float* __restrict__ lib) {
    __shared__ unsigned long long wmax[12];
    __shared__ int sidx_s, midx_s;
    int t = threadIdx.x, w = t >> 5, lane = t & 31;   // 384 threads
    unsigned long long best = 0;
    for (int i = t; i < NPATCH; i += 384) {
        unsigned long long p = g_minpack[i];
        unsigned long long key = (p & 0xFFFFFFFF00000000ull) | (unsigned int)(0xFFFFFFFFu - (unsigned int)i);
        best = (key > best) ? key : best;
    }
    #pragma unroll
    for (int o = 16; o > 0; o >>= 1) {
        unsigned long long v = __shfl_down_sync(0xffffffffu, best, o);
        best = (v > best) ? v : best;
    }
    if (lane == 0) wmax[w] = best;
    __syncthreads();
    if (t == 0) {
        unsigned long long b = 0;
        #pragma unroll
        for (int i = 0; i < 12; i++) b = (wmax[i] > b) ? wmax[i] : b;
        int si = (int)(0xFFFFFFFFu - (unsigned int)(b & 0xFFFFFFFFu));
        unsigned long long p = g_minpack[si];
        int mi = (int)(unsigned int)(p & 0xFFFFFFFFu);
        g_scal.s_idx = si; g_scal.s_star = sqrtf(__uint_as_float((unsigned int)(p >> 32)));
        g_scal.m_idx = mi; g_scal.msn = g_ln[mi];
        sidx_s = si; midx_s = mi;
    }
    __syncthreads();
    for (int c = t; c < DDIM; c += 384) {
        g_mt[c] = g_patchN[sidx_s * DDIM + c];
        g_ms[c] = lib[(size_t)midx_s * DDIM + c];
    }
}

// ---------------- K6: d_star (fp32) ----------------
__global__ void k_dstar(const float* __restrict__ lib) {
    __shared__ float ms[DDIM];
    for (int c = threadIdx.x; c < DDIM; c += 256) ms[c] = g_ms[c];
    __syncthreads();
    int row = blockIdx.x * 8 + (threadIdx.x >> 5), lane = threadIdx.x & 31;
    const float* p = lib + (size_t)row * DDIM;
    float s = 0.f;
    for (int c = lane; c < DDIM; c += 32) s += p[c] * ms[c];
    #pragma unroll
    for (int o = 16; o > 0; o >>= 1) s += __shfl_down_sync(0xffffffffu, s, o);
    if (lane == 0) g_dstar[row] = fmaxf(g_ln[row] + g_scal.msn - 2.f * s, 0.f);
}

// ---------------- K7: top-5 ----------------
__device__ __forceinline__ void merge5(unsigned long long* a, const unsigned long long* b) {
    unsigned long long o[5]; int ia = 0, ib = 0;
    #pragma unroll
    for (int k = 0; k < 5; k++) {
        unsigned long long va = a[ia], vb = b[ib];
        if (va <= vb) { o[k] = va; ia++; } else { o[k] = vb; ib++; }
    }
    #pragma unroll
    for (int k = 0; k < 5; k++) a[k] = o[k];
}
__global__ void k_top5() {
    __shared__ unsigned long long L[1024 * 5];
    int tid = threadIdx.x;
    unsigned long long arr[5];
    #pragma unroll
    for (int k = 0; k < 5; k++) arr[k] = ~0ull;
    for (int j = tid; j < MLIB; j += 1024) {
        unsigned long long p = ((unsigned long long)__float_as_uint(g_dstar[j]) << 32) | (unsigned int)j;
        if (p < arr[4]) {
            arr[4] = p;
            #pragma unroll
            for (int k = 4; k > 0; k--)
                if (arr[k] < arr[k - 1]) { unsigned long long t = arr[k]; arr[k] = arr[k - 1]; arr[k - 1] = t; }
        }
    }
    #pragma unroll
    for (int k = 0; k < 5; k++) L[tid * 5 + k] = arr[k];
    __syncthreads();
    for (int s = 512; s > 0; s >>= 1) {
        if (tid < s) merge5(&L[tid * 5], &L[(tid + s) * 5]);
        __syncthreads();
    }
    if (tid == 0)
        #pragma unroll
        for (int k = 0; k < 5; k++) g_nn[k] = (int)(unsigned int)(L[k] & 0xffffffffu);
}

// ---------------- K8: final scalar ----------------
__global__ void k_final(const float* __restrict__ lib, float* __restrict__ out) {
    __shared__ float res[6];
    int w = threadIdx.x >> 5, lane = threadIdx.x & 31;
    float part = 0.f;
    if (w < KTOP) {
        const float* p = lib + (size_t)g_nn[w] * DDIM;
        for (int c = lane; c < DDIM; c += 32) { float d = g_mt[c] - p[c]; part += d * d; }
    } else {
        for (int c = lane; c < DDIM; c += 32) { float d = g_mt[c] - g_ms[c]; part += d * d; }
    }
    #pragma unroll
    for (int o = 16; o > 0; o >>= 1) part += __shfl_down_sync(0xffffffffu, part, o);
    if (lane == 0) res[w] = sqrtf(part);
    __syncthreads();
    if (threadIdx.x == 0) {
        float num = expf(res[5]), den = 0.f;
        #pragma unroll
        for (int k = 0; k < KTOP; k++) den += expf(res[k]);
        out[0] = (1.f - num / den) * g_scal.s_star;
    }
}

// ---------------- K9: resize, K10/K11: blur ----------------
__device__ __forceinline__ float minval_at(int y, int x) {
    return sqrtf(__uint_as_float((unsigned int)(g_minpack[y * HWDIM + x] >> 32)));
}
__global__ void k_resize() {
    int idx = blockIdx.x * 256 + threadIdx.x;
    if (idx >= IMG * IMG) return;
    int oy = idx / IMG, ox = idx % IMG;
    const float sc = (float)HWDIM / (float)IMG;
    float fy = fmaxf((oy + 0.5f) * sc - 0.5f, 0.f);
    float fx = fmaxf((ox + 0.5f) * sc - 0.5f, 0.f);
    int y0 = min((int)fy, HWDIM - 1), x0 = min((int)fx, HWDIM - 1);
    float wy = fy - y0, wx = fx - x0;
    int y1 = min(y0 + 1, HWDIM - 1), x1 = min(x0 + 1, HWDIM - 1);
    g_map1[idx] = (1.f - wy) * ((1.f - wx) * minval_at(y0, x0) + wx * minval_at(y0, x1))
                +        wy  * ((1.f - wx) * minval_at(y1, x0) + wx * minval_at(y1, x1));
}
__device__ __forceinline__ int reflect_idx(int i) {
    if (i < 0) i = -i;
    if (i > IMG - 1) i = 2 * (IMG - 1) - i;
    return i;
}
__global__ void k_blurV() {
    int idx = blockIdx.x * 256 + threadIdx.x;
    if (idx >= IMG * IMG) return;
    int oy = idx / IMG, ox = idx % IMG;
    float ws = 0.f, acc = 0.f;
    #pragma unroll
    for (int j = -KRAD; j <= KRAD; j++) {
        float w = expf(-0.5f * ((float)j / SIGMA) * ((float)j / SIGMA));
        ws += w; acc += w * g_map1[reflect_idx(oy + j) * IMG + ox];
    }
    g_map2[idx] = acc / ws;
}
__global__ void k_blurH(float* __restrict__ out) {
    int idx = blockIdx.x * 256 + threadIdx.x;
    if (idx >= IMG * IMG) return;
    int oy = idx / IMG, ox = idx % IMG;
    float ws = 0.f, acc = 0.f;
    #pragma unroll
    for (int j = -KRAD; j <= KRAD; j++) {
        float w = expf(-0.5f * ((float)j / SIGMA) * ((float)j / SIGMA));
        ws += w; acc += w * g_map2[oy * IMG + reflect_idx(ox + j)];
    }
    out[1 + idx] = acc / ws;
}

// ---------------- launch ----------------
extern "C" void kernel_launch(void* const* d_in, const int* in_sizes, int n_in,
                              void* d_out, int out_size) {
    const float* patch = (const float*)d_in[0];
    const float* lib   = (const float*)d_in[1];
    float* out = (float*)d_out;

    cudaFuncSetAttribute(k_gemm, cudaFuncAttributeMaxDynamicSharedMemorySize, SMEMG);

    k_norm<<<NPAD, 128>>>(patch);
    k_splitP<<<NPAD / 8, 256>>>();
    k_split<<<MPAD / 8, 256>>>(lib);
    {
        dim3 grid(NPAD / GTM, MPAD / GTN);   // (6, 1563); x fast -> patch tiles L2-resident
        k_gemm<<<grid, 256, SMEMG>>>();
    }
    k_select<<<1, 384>>>(lib);
    k_dstar<<<MLIB / 8, 256>>>(lib);
    k_top5<<<1, 1024>>>();
    k_final<<<1, 192>>>(lib, out);
    k_resize<<<(IMG * IMG + 255) / 256, 256>>>();
    k_blurV<<<(IMG * IMG + 255) / 256, 256>>>();
    k_blurH<<<(IMG * IMG + 255) / 256, 256>>>(out);
}